// round 15
// baseline (speedup 1.0000x reference)
#include <cuda_runtime.h>

#define BATCH 16
#define NPTS  2048
#define CDIM  64
#define ODIM  64
#define KNN   20
#define ROWS_TOTAL (BATCH*NPTS)   // 32768
#define NEG_INF (-3.402823466e38f)
#define FULLMASK 0xffffffffu

typedef unsigned long long ull;

// packed f32x2 helpers (sm_100+; ptxas never emits FFMA2 from C++)
#define LDS2(a0, a1, addr) \
    asm("ld.shared.v2.u64 {%0,%1},[%2];" : "=l"(a0), "=l"(a1) : "r"(addr))
#define LDS1(a0, addr) \
    asm("ld.shared.b64 %0,[%1];" : "=l"(a0) : "r"(addr))
#define FMA2(d, a, b) \
    asm("fma.rn.f32x2 %0, %1, %2, %0;" : "+l"(d) : "l"(a), "l"(b))
#define UNPACK2(lo, hi, v) \
    asm("mov.b64 {%0,%1}, %2;" : "=f"(lo), "=f"(hi) : "l"(v))
#define PACKDUP(d, f) \
    asm("mov.b64 %0, {%1,%1};" : "=l"(d) : "f"(f))

// ---------------- scratch (static device globals; no allocation) ----------------
__device__ float  g_xx[ROWS_TOTAL];
__device__ float4 g_xpair[BATCH * 16 * 64 * 32];   // 8 MB: swizzled col-pair tiles
__device__ float  g_hc[ROWS_TOTAL*ODIM];
__device__ float  g_hn[ROWS_TOTAL*ODIM];
__device__ float  g_mmax[ROWS_TOTAL*ODIM];
__device__ float  g_mmin[ROWS_TOTAL*ODIM];
__device__ double g_sum[ODIM];
__device__ double g_sumsq[ODIM];
__device__ float  g_scale[ODIM];
__device__ float  g_shift[ODIM];

// ---------------- K1: row squared norms (unchanged numerics) ----------------
__global__ void k_xx(const float* __restrict__ x) {
    int row  = blockIdx.x * 4 + (threadIdx.x >> 5);
    int lane = threadIdx.x & 31;
    const float2* x2 = (const float2*)(x + (size_t)row * CDIM);
    float2 v = x2[lane];
    float s = v.x * v.x + v.y * v.y;
    #pragma unroll
    for (int o = 16; o; o >>= 1) s += __shfl_down_sync(FULLMASK, s, o);
    if (lane == 0) g_xx[row] = s;
}

// ---------------- K1b: build swizzled col-pair tiles; zero BN accumulators ----------------
__global__ void k_pack(const float* __restrict__ x) {
    if (blockIdx.x == 0 && threadIdx.x < ODIM) {
        g_sum[threadIdx.x] = 0.0; g_sumsq[threadIdx.x] = 0.0;
    }
    int idx = blockIdx.x * 256 + threadIdx.x;      // 2^18 total
    int cq = idx & 15, p = (idx >> 4) & 63, ct = (idx >> 10) & 15, b = idx >> 14;
    const float4* xg4 = (const float4*)x;
    int rv = b * NPTS + ct * 128 + p;
    int rw = rv + 64;
    float4 v = xg4[(size_t)rv * 16 + cq];
    float4 w = xg4[(size_t)rw * 16 + cq];
    int px = p & 31;
    size_t base = ((size_t)(b * 16 + ct) * 64 + p) * 32;
    g_xpair[base + ((2 * cq) ^ px)]     = make_float4(v.x, w.x, v.y, w.y);
    g_xpair[base + ((2 * cq + 1) ^ px)] = make_float4(v.z, w.z, v.w, w.w);
}

// ---------------- K2: hc = x@W1^T + b, hn = x@W2^T  (32 rows/block) ----------------
__global__ void k_hchn(const float* __restrict__ x, const float* __restrict__ W,
                       const float* __restrict__ bias) {
    extern __shared__ float sm[];
    float4* Wt4 = (float4*)sm;          // [128*17]
    float4* rX4 = Wt4 + 128 * 17;       // [32*16]
    int t = threadIdx.x;
    int rowbase = blockIdx.x * 32;
    const float4* Wg4 = (const float4*)W;
    const float4* xg4 = (const float4*)x;

    #pragma unroll 2
    for (int li = t; li < 128 * 16; li += 256) {
        int cq = li & 15, p = li >> 4;
        Wt4[p * 17 + cq] = (p < 64) ? Wg4[p * 32 + cq] : Wg4[(p - 64) * 32 + 16 + cq];
    }
    for (int li = t; li < 32 * 16; li += 256) {
        int cq = li & 15, r = li >> 4;
        rX4[r * 16 + cq] = xg4[(size_t)(rowbase + r) * 16 + cq];
    }
    __syncthreads();

    int warp = t >> 5, j = t & 31;
    int rl0 = warp * 4;
    float acc[4][4];
    #pragma unroll
    for (int r = 0; r < 4; r++)
        #pragma unroll
        for (int q = 0; q < 4; q++) acc[r][q] = 0.f;

    #pragma unroll
    for (int cq = 0; cq < 16; cq++) {
        float4 c0 = Wt4[(j     ) * 17 + cq];
        float4 c1 = Wt4[(j + 32) * 17 + cq];
        float4 c2 = Wt4[(j + 64) * 17 + cq];
        float4 c3 = Wt4[(j + 96) * 17 + cq];
        #pragma unroll
        for (int r = 0; r < 4; r++) {
            float4 rv = rX4[(rl0 + r) * 16 + cq];
            acc[r][0] = fmaf(rv.w, c0.w, fmaf(rv.z, c0.z, fmaf(rv.y, c0.y, fmaf(rv.x, c0.x, acc[r][0]))));
            acc[r][1] = fmaf(rv.w, c1.w, fmaf(rv.z, c1.z, fmaf(rv.y, c1.y, fmaf(rv.x, c1.x, acc[r][1]))));
            acc[r][2] = fmaf(rv.w, c2.w, fmaf(rv.z, c2.z, fmaf(rv.y, c2.y, fmaf(rv.x, c2.x, acc[r][2]))));
            acc[r][3] = fmaf(rv.w, c3.w, fmaf(rv.z, c3.z, fmaf(rv.y, c3.y, fmaf(rv.x, c3.x, acc[r][3]))));
        }
    }
    #pragma unroll
    for (int q = 0; q < 4; q++) {
        int p = j + 32 * q;
        float bv = (p < 64) ? bias[p] : 0.f;
        #pragma unroll
        for (int r = 0; r < 4; r++) {
            int row = rowbase + rl0 + r;
            if (p < 64) g_hc[(size_t)row * 64 + p] = acc[r][q] + bv;
            else        g_hn[(size_t)row * 64 + (p - 64)] = acc[r][q];
        }
    }
}

// ---------------- K3: fused Gram + top-20 + gather/stats epilogue ----------------
// 256 threads = 8 warps, 64 rows/block (8 rows/warp), col tiles of 128.
// Col-read bytes per row HALVED vs R14 (each warp reads the 32KB col tile for
// 8 rows instead of 4). Rows stored undup (16KB); per-(cq,m) each row costs
// one LDS.64 broadcast + 2 mov.b64 packs. Operand values and FMA2 k-order
// identical to R12..R14 -> distances bitwise-identical. 48KB static SMEM,
// launch_bounds(256,3): 3 CTAs/SM.
__global__ void __launch_bounds__(256, 3) k_topk(const float* __restrict__ x) {
    __shared__ float4 rX4s[64 * 16];  // plain rows         (16 KB)
    __shared__ float4 cP4[64 * 32];   // col pairs swizzled (32 KB)

    int t = threadIdx.x;
    int b = blockIdx.y;
    int rowbase = b * NPTS + blockIdx.x * 64;

    // plain row tile: rows are contiguous in x -> straight linear copy
    {
        const float4* rsrc = (const float4*)x + (size_t)rowbase * 16;
        #pragma unroll
        for (int i = 0; i < 4; i++) rX4s[t + 256 * i] = rsrc[t + 256 * i];
    }

    int warp = t >> 5, j = t & 31;
    int rl0 = warp * 8;

    unsigned sbr = (unsigned)__cvta_generic_to_shared(rX4s);
    unsigned sbc = (unsigned)__cvta_generic_to_shared(cP4);
    unsigned rWbase = sbr + (unsigned)(rl0 * 256);   // row stride 64 floats = 256B
    unsigned cp0 = sbc + (unsigned)(j * 512);        // pair (j, j+64)
    unsigned cp1 = cp0 + 32u * 512u;                 // pair (j+32, j+96)

    float lv[8]; int lidx[8];
    #pragma unroll
    for (int r = 0; r < 8; r++) { lv[r] = NEG_INF; lidx[r] = 0; }

    for (int ct = 0; ct < 16; ct++) {
        int cb = ct * 128;
        __syncthreads();
        // col-pair tile: linear copy (coalesced LDG, conflict-free STS.128)
        {
            const float4* src = g_xpair + (size_t)(b * 16 + ct) * 64 * 32;
            #pragma unroll
            for (int i = 0; i < 8; i++) cP4[t + 256 * i] = src[t + 256 * i];
        }
        __syncthreads();

        ull A[8][2];
        #pragma unroll
        for (int r = 0; r < 8; r++) { A[r][0] = 0ull; A[r][1] = 0ull; }

        #pragma unroll 2
        for (int cq = 0; cq < 16; cq++) {
            #pragma unroll
            for (int m = 0; m < 2; m++) {
                unsigned slot = (unsigned)(((2 * cq + m) ^ j) * 16);
                ull a0, a1, b0, b1;
                LDS2(a0, a1, cp0 + slot);   // cols (cb+j,    cb+j+64) : k, k+1
                LDS2(b0, b1, cp1 + slot);   // cols (cb+j+32, cb+j+96) : k, k+1
                unsigned rof = rWbase + (unsigned)((2 * cq + m) * 8);
                #pragma unroll
                for (int r = 0; r < 8; r++) {
                    ull v; float f0, f1; ull d0, d1;
                    LDS1(v, rof + (unsigned)(r * 256));   // (x_rk, x_rk1) undup
                    UNPACK2(f0, f1, v);
                    PACKDUP(d0, f0);                      // (x_rk,  x_rk)
                    PACKDUP(d1, f1);                      // (x_rk1, x_rk1)
                    FMA2(A[r][0], a0, d0); FMA2(A[r][1], b0, d0);
                    FMA2(A[r][0], a1, d1); FMA2(A[r][1], b1, d1);
                }
            }
        }

        float xq0 = __ldg(&g_xx[b * NPTS + cb + j]);
        float xq1 = __ldg(&g_xx[b * NPTS + cb + j + 32]);
        float xq2 = __ldg(&g_xx[b * NPTS + cb + j + 64]);
        float xq3 = __ldg(&g_xx[b * NPTS + cb + j + 96]);

        #pragma unroll
        for (int r = 0; r < 8; r++) {
            float lo0, hi0, lo1, hi1;
            UNPACK2(lo0, hi0, A[r][0]);
            UNPACK2(lo1, hi1, A[r][1]);
            float cnd0 = fmaf(-2.f, lo0, xq0);
            float cnd1 = fmaf(-2.f, lo1, xq1);
            float cnd2 = fmaf(-2.f, hi0, xq2);
            float cnd3 = fmaf(-2.f, hi1, xq3);
            float thr = __shfl_sync(FULLMASK, lv[r], KNN - 1);
            float rmax = fmaxf(fmaxf(cnd0, cnd1), fmaxf(cnd2, cnd3));
            if (__ballot_sync(FULLMASK, rmax > thr) == 0u) continue;

            #pragma unroll
            for (int q = 0; q < 4; q++) {
                float cand = (q == 0) ? cnd0 : (q == 1) ? cnd1 : (q == 2) ? cnd2 : cnd3;
                int   col  = cb + j + 32 * q;
                unsigned mask = __ballot_sync(FULLMASK, cand > thr);
                if (mask) {   // warp-uniform; thr only changes when inserts happen
                    while (mask) {
                        int src = __ffs(mask) - 1; mask &= mask - 1;
                        float val = __shfl_sync(FULLMASK, cand, src);
                        int   ci  = __shfl_sync(FULLMASK, col,  src);
                        float pv  = __shfl_up_sync(FULLMASK, lv[r], 1);
                        int   pi  = __shfl_up_sync(FULLMASK, lidx[r], 1);
                        bool keep = (lv[r] >= val);
                        bool prevkeep = (j == 0) || (pv >= val);
                        if (!keep) {
                            lv[r]   = prevkeep ? val : pv;
                            lidx[r] = prevkeep ? ci  : pi;
                        }
                    }
                    thr = __shfl_sync(FULLMASK, lv[r], KNN - 1);
                }
            }
        }
    }

    // ---- fused epilogue: former k_stats over 64 rows ----
    __syncthreads();                       // all warps done reading rX4s/cP4
    int* sidx = (int*)rX4s;                // reuse dead smem (64*20 ints = 5KB)
    #pragma unroll
    for (int r = 0; r < 8; r++)
        if (j < KNN) sidx[(rl0 + r) * KNN + j] = lidx[r];
    __syncthreads();

    {
        int tx = t & 63, ty = t >> 6;
        float* ssum = (float*)cP4;         // [4*64]
        float* sssq = ssum + 256;
        float sum = 0.f, ssq = 0.f;
        for (int ri = ty; ri < 64; ri += 4) {
            int row = rowbase + ri;
            float hcv = g_hc[(size_t)row * 64 + tx];
            float mx = NEG_INF, mn = -NEG_INF;
            #pragma unroll
            for (int k = 0; k < KNN; k++) {
                int jj = sidx[ri * KNN + k];
                float v = hcv + g_hn[(size_t)(b * NPTS + jj) * 64 + tx];
                sum += v; ssq = fmaf(v, v, ssq);
                mx = fmaxf(mx, v); mn = fminf(mn, v);
            }
            g_mmax[(size_t)row * 64 + tx] = mx;
            g_mmin[(size_t)row * 64 + tx] = mn;
        }
        ssum[ty * 64 + tx] = sum; sssq[ty * 64 + tx] = ssq;
        __syncthreads();
        if (ty == 0) {
            float s = ssum[tx] + ssum[64 + tx] + ssum[128 + tx] + ssum[192 + tx];
            float q = sssq[tx] + sssq[64 + tx] + sssq[128 + tx] + sssq[192 + tx];
            atomicAdd(&g_sum[tx],   (double)s);
            atomicAdd(&g_sumsq[tx], (double)q);
        }
    }
}

// ---------------- K5: finalize BN scale/shift ----------------
__global__ void k_final(const float* __restrict__ gamma, const float* __restrict__ beta) {
    int o = threadIdx.x;
    if (o < ODIM) {
        double cnt  = (double)ROWS_TOTAL * KNN;
        double mean = g_sum[o] / cnt;
        double var  = g_sumsq[o] / cnt - mean * mean;
        float sc = gamma[o] * rsqrtf((float)var + 1e-5f);
        g_scale[o] = sc;
        g_shift[o] = beta[o] - (float)mean * sc;
    }
}

// ---------------- K6: apply affine + LeakyReLU + transpose to [B,O,N] ----------------
__global__ void k_out(float* __restrict__ out) {
    __shared__ float smt[64][65];
    int tx = threadIdx.x, ty = threadIdx.y;   // block (64,4)
    int nb = blockIdx.x * 64;
    int b  = blockIdx.y;
    float sc = g_scale[tx], sh = g_shift[tx];
    #pragma unroll
    for (int i = 0; i < 16; i++) {
        int nl = ty + 4 * i;
        size_t rowoff = (size_t)(b * NPTS + nb + nl) * 64 + tx;
        float m = (sc >= 0.f) ? g_mmax[rowoff] : g_mmin[rowoff];
        float y = fmaf(m, sc, sh);
        y = (y >= 0.f) ? y : 0.2f * y;
        smt[nl][tx] = y;
    }
    __syncthreads();
    #pragma unroll
    for (int i = 0; i < 16; i++) {
        int o = ty + 4 * i;
        out[((size_t)(b * 64 + o)) * NPTS + nb + tx] = smt[tx][o];
    }
}

extern "C" void kernel_launch(void* const* d_in, const int* in_sizes, int n_in,
                              void* d_out, int out_size) {
    const float* x     = (const float*)d_in[0];
    const float* W     = (const float*)d_in[1];
    const float* bias  = (const float*)d_in[2];
    const float* gamma = (const float*)d_in[3];
    const float* beta  = (const float*)d_in[4];
    float* out = (float*)d_out;

    k_xx<<<ROWS_TOTAL / 4, 128>>>(x);
    k_pack<<<1024, 256>>>(x);
    k_hchn<<<ROWS_TOTAL / 32, 256, (128 * 17 + 32 * 16) * 16>>>(x, W, bias);
    k_topk<<<dim3(NPTS / 64, BATCH), 256>>>(x);
    k_final<<<1, 64>>>(gamma, beta);
    k_out<<<dim3(NPTS / 64, BATCH), dim3(64, 4)>>>(out);
}

// round 16
// speedup vs baseline: 1.4696x; 1.4696x over previous
#include <cuda_runtime.h>

#define BATCH 16
#define NPTS  2048
#define CDIM  64
#define ODIM  64
#define KNN   20
#define ROWS_TOTAL (BATCH*NPTS)   // 32768
#define NEG_INF (-3.402823466e38f)
#define FULLMASK 0xffffffffu
#define COLTILE_BYTES 32768u

typedef unsigned long long ull;

// packed f32x2 helpers (sm_100+; ptxas never emits FFMA2 from C++)
#define LDS2(a0, a1, addr) \
    asm("ld.shared.v2.u64 {%0,%1},[%2];" : "=l"(a0), "=l"(a1) : "r"(addr))
#define LDS1(a0, addr) \
    asm("ld.shared.b64 %0,[%1];" : "=l"(a0) : "r"(addr))
#define FMA2(d, a, b) \
    asm("fma.rn.f32x2 %0, %1, %2, %0;" : "+l"(d) : "l"(a), "l"(b))
#define UNPACK2(lo, hi, v) \
    asm("mov.b64 {%0,%1}, %2;" : "=f"(lo), "=f"(hi) : "l"(v))
#define PACKDUP(d, f) \
    asm("mov.b64 %0, {%1,%1};" : "=l"(d) : "f"(f))

// mbarrier + bulk-copy helpers
#define MBAR_INIT(mbar) \
    asm volatile("mbarrier.init.shared.b64 [%0], 1;" :: "r"(mbar) : "memory")
#define MBAR_EXPECT_TX(mbar, bytes) \
    asm volatile("mbarrier.arrive.expect_tx.shared.b64 _, [%0], %1;" \
                 :: "r"(mbar), "r"(bytes) : "memory")
#define BULK_G2S(smem_dst, gmem_src, bytes, mbar) \
    asm volatile("cp.async.bulk.shared::cta.global.mbarrier::complete_tx::bytes " \
                 "[%0], [%1], %2, [%3];" \
                 :: "r"(smem_dst), "l"(gmem_src), "r"(bytes), "r"(mbar) : "memory")
#define MBAR_WAIT(mbar, parity) do {                                        \
    unsigned _done;                                                         \
    asm volatile("{\n\t.reg .pred p;\n\t"                                   \
        "mbarrier.try_wait.parity.acquire.cta.shared::cta.b64 p, [%1], %2;\n\t" \
        "selp.b32 %0, 1, 0, p;\n\t}"                                        \
        : "=r"(_done) : "r"(mbar), "r"(parity) : "memory");                 \
    if (!_done) {                                                           \
        asm volatile("{\n\t.reg .pred P1;\n\t"                              \
            "WL_%=:\n\t"                                                    \
            "mbarrier.try_wait.parity.acquire.cta.shared::cta.b64 P1, [%0], %1, 0x989680;\n\t" \
            "@P1 bra.uni WD_%=;\n\t"                                        \
            "bra.uni WL_%=;\n\t"                                            \
            "WD_%=:\n\t}"                                                   \
            :: "r"(mbar), "r"(parity) : "memory");                          \
    }                                                                       \
} while (0)

// ---------------- scratch (static device globals; no allocation) ----------------
__device__ float  g_xx[ROWS_TOTAL];
__device__ float4 g_xpair[BATCH * 16 * 64 * 32];   // 8 MB: swizzled col-pair tiles
__device__ float  g_hc[ROWS_TOTAL*ODIM];
__device__ float  g_hn[ROWS_TOTAL*ODIM];
__device__ float  g_mmax[ROWS_TOTAL*ODIM];
__device__ float  g_mmin[ROWS_TOTAL*ODIM];
__device__ double g_sum[ODIM];
__device__ double g_sumsq[ODIM];
__device__ float  g_scale[ODIM];
__device__ float  g_shift[ODIM];

// ---------------- K1: row squared norms (unchanged numerics) ----------------
__global__ void k_xx(const float* __restrict__ x) {
    int row  = blockIdx.x * 4 + (threadIdx.x >> 5);
    int lane = threadIdx.x & 31;
    const float2* x2 = (const float2*)(x + (size_t)row * CDIM);
    float2 v = x2[lane];
    float s = v.x * v.x + v.y * v.y;
    #pragma unroll
    for (int o = 16; o; o >>= 1) s += __shfl_down_sync(FULLMASK, s, o);
    if (lane == 0) g_xx[row] = s;
}

// ---------------- K1b: build swizzled col-pair tiles; zero BN accumulators ----------------
__global__ void k_pack(const float* __restrict__ x) {
    if (blockIdx.x == 0 && threadIdx.x < ODIM) {
        g_sum[threadIdx.x] = 0.0; g_sumsq[threadIdx.x] = 0.0;
    }
    int idx = blockIdx.x * 256 + threadIdx.x;      // 2^18 total
    int cq = idx & 15, p = (idx >> 4) & 63, ct = (idx >> 10) & 15, b = idx >> 14;
    const float4* xg4 = (const float4*)x;
    int rv = b * NPTS + ct * 128 + p;
    int rw = rv + 64;
    float4 v = xg4[(size_t)rv * 16 + cq];
    float4 w = xg4[(size_t)rw * 16 + cq];
    int px = p & 31;
    size_t base = ((size_t)(b * 16 + ct) * 64 + p) * 32;
    g_xpair[base + ((2 * cq) ^ px)]     = make_float4(v.x, w.x, v.y, w.y);
    g_xpair[base + ((2 * cq + 1) ^ px)] = make_float4(v.z, w.z, v.w, w.w);
}

// ---------------- K2: hc = x@W1^T + b, hn = x@W2^T  (32 rows/block) ----------------
__global__ void k_hchn(const float* __restrict__ x, const float* __restrict__ W,
                       const float* __restrict__ bias) {
    extern __shared__ float sm[];
    float4* Wt4 = (float4*)sm;          // [128*17]
    float4* rX4 = Wt4 + 128 * 17;       // [32*16]
    int t = threadIdx.x;
    int rowbase = blockIdx.x * 32;
    const float4* Wg4 = (const float4*)W;
    const float4* xg4 = (const float4*)x;

    #pragma unroll 2
    for (int li = t; li < 128 * 16; li += 256) {
        int cq = li & 15, p = li >> 4;
        Wt4[p * 17 + cq] = (p < 64) ? Wg4[p * 32 + cq] : Wg4[(p - 64) * 32 + 16 + cq];
    }
    for (int li = t; li < 32 * 16; li += 256) {
        int cq = li & 15, r = li >> 4;
        rX4[r * 16 + cq] = xg4[(size_t)(rowbase + r) * 16 + cq];
    }
    __syncthreads();

    int warp = t >> 5, j = t & 31;
    int rl0 = warp * 4;
    float acc[4][4];
    #pragma unroll
    for (int r = 0; r < 4; r++)
        #pragma unroll
        for (int q = 0; q < 4; q++) acc[r][q] = 0.f;

    #pragma unroll
    for (int cq = 0; cq < 16; cq++) {
        float4 c0 = Wt4[(j     ) * 17 + cq];
        float4 c1 = Wt4[(j + 32) * 17 + cq];
        float4 c2 = Wt4[(j + 64) * 17 + cq];
        float4 c3 = Wt4[(j + 96) * 17 + cq];
        #pragma unroll
        for (int r = 0; r < 4; r++) {
            float4 rv = rX4[(rl0 + r) * 16 + cq];
            acc[r][0] = fmaf(rv.w, c0.w, fmaf(rv.z, c0.z, fmaf(rv.y, c0.y, fmaf(rv.x, c0.x, acc[r][0]))));
            acc[r][1] = fmaf(rv.w, c1.w, fmaf(rv.z, c1.z, fmaf(rv.y, c1.y, fmaf(rv.x, c1.x, acc[r][1]))));
            acc[r][2] = fmaf(rv.w, c2.w, fmaf(rv.z, c2.z, fmaf(rv.y, c2.y, fmaf(rv.x, c2.x, acc[r][2]))));
            acc[r][3] = fmaf(rv.w, c3.w, fmaf(rv.z, c3.z, fmaf(rv.y, c3.y, fmaf(rv.x, c3.x, acc[r][3]))));
        }
    }
    #pragma unroll
    for (int q = 0; q < 4; q++) {
        int p = j + 32 * q;
        float bv = (p < 64) ? bias[p] : 0.f;
        #pragma unroll
        for (int r = 0; r < 4; r++) {
            int row = rowbase + rl0 + r;
            if (p < 64) g_hc[(size_t)row * 64 + p] = acc[r][q] + bv;
            else        g_hn[(size_t)row * 64 + (p - 64)] = acc[r][q];
        }
    }
}

// ---------------- K3: fused Gram + top-20 + gather/stats epilogue ----------------
// R14 shape (best: 256 thr, 8 warps, 32 rows/block, 4 rows/warp, undup rows).
// NEW: col-tile fill via single-buffered cp.async.bulk + mbarrier. The copy
// for tile ct+1 is issued right after the post-GEMM barrier and overlaps the
// candidate/insert phase. GEMM datapath, k-order, insert logic unchanged ->
// distances bitwise-identical to R12/R14.
__global__ void __launch_bounds__(256, 4) k_topk(const float* __restrict__ x) {
    __shared__ float4 rX4s[32 * 16];                 // plain rows (8 KB)
    __shared__ float4 cP4[64 * 32];                  // col pairs swizzled (32 KB)
    __shared__ alignas(8) unsigned long long s_mbar;

    int t = threadIdx.x;
    int b = blockIdx.y;
    int rowbase = b * NPTS + blockIdx.x * 32;

    // plain row tile: rows are contiguous in x -> straight linear copy
    {
        const float4* rsrc = (const float4*)x + (size_t)rowbase * 16;
        rX4s[t]       = rsrc[t];
        rX4s[t + 256] = rsrc[t + 256];
    }

    int warp = t >> 5, j = t & 31;
    int rl0 = warp * 4;

    unsigned sbr  = (unsigned)__cvta_generic_to_shared(rX4s);
    unsigned sbc  = (unsigned)__cvta_generic_to_shared(cP4);
    unsigned mbar = (unsigned)__cvta_generic_to_shared(&s_mbar);
    unsigned rWbase = sbr + (unsigned)(rl0 * 256);   // row stride 64 floats = 256B
    unsigned cp0 = sbc + (unsigned)(j * 512);        // pair (j, j+64)
    unsigned cp1 = cp0 + 32u * 512u;                 // pair (j+32, j+96)

    const float4* tiles = g_xpair + (size_t)b * 16 * 64 * 32;

    if (t == 0) MBAR_INIT(mbar);
    __syncthreads();
    if (t == 0) {
        MBAR_EXPECT_TX(mbar, COLTILE_BYTES);
        BULK_G2S(sbc, tiles, COLTILE_BYTES, mbar);   // tile 0
    }

    float lv[4]; int lidx[4];
    #pragma unroll
    for (int r = 0; r < 4; r++) { lv[r] = NEG_INF; lidx[r] = 0; }

    for (int ct = 0; ct < 16; ct++) {
        int cb = ct * 128;
        MBAR_WAIT(mbar, ct & 1);                     // tile ct data ready

        ull A[4][2];
        #pragma unroll
        for (int r = 0; r < 4; r++) { A[r][0] = 0ull; A[r][1] = 0ull; }

        #pragma unroll 4
        for (int cq = 0; cq < 16; cq++) {
            #pragma unroll
            for (int m = 0; m < 2; m++) {
                unsigned slot = (unsigned)(((2 * cq + m) ^ j) * 16);
                ull a0, a1, b0, b1;
                LDS2(a0, a1, cp0 + slot);   // cols (cb+j,    cb+j+64) : k, k+1
                LDS2(b0, b1, cp1 + slot);   // cols (cb+j+32, cb+j+96) : k, k+1
                unsigned rof = rWbase + (unsigned)((2 * cq + m) * 8);
                #pragma unroll
                for (int r = 0; r < 4; r++) {
                    ull v; float f0, f1; ull d0, d1;
                    LDS1(v, rof + (unsigned)(r * 256));   // (x_rk, x_rk1) undup
                    UNPACK2(f0, f1, v);
                    PACKDUP(d0, f0);                      // (x_rk,  x_rk)
                    PACKDUP(d1, f1);                      // (x_rk1, x_rk1)
                    FMA2(A[r][0], a0, d0); FMA2(A[r][1], b0, d0);
                    FMA2(A[r][0], a1, d1); FMA2(A[r][1], b1, d1);
                }
            }
        }

        __syncthreads();                             // all warps done reading cP4
        if (ct + 1 < 16 && t == 0) {                 // overlap next copy w/ inserts
            MBAR_EXPECT_TX(mbar, COLTILE_BYTES);
            BULK_G2S(sbc, tiles + (size_t)(ct + 1) * 64 * 32, COLTILE_BYTES, mbar);
        }

        float xq0 = __ldg(&g_xx[b * NPTS + cb + j]);
        float xq1 = __ldg(&g_xx[b * NPTS + cb + j + 32]);
        float xq2 = __ldg(&g_xx[b * NPTS + cb + j + 64]);
        float xq3 = __ldg(&g_xx[b * NPTS + cb + j + 96]);

        #pragma unroll
        for (int r = 0; r < 4; r++) {
            float lo0, hi0, lo1, hi1;
            UNPACK2(lo0, hi0, A[r][0]);
            UNPACK2(lo1, hi1, A[r][1]);
            float cnd0 = fmaf(-2.f, lo0, xq0);
            float cnd1 = fmaf(-2.f, lo1, xq1);
            float cnd2 = fmaf(-2.f, hi0, xq2);
            float cnd3 = fmaf(-2.f, hi1, xq3);
            float thr = __shfl_sync(FULLMASK, lv[r], KNN - 1);
            float rmax = fmaxf(fmaxf(cnd0, cnd1), fmaxf(cnd2, cnd3));
            if (__ballot_sync(FULLMASK, rmax > thr) == 0u) continue;

            #pragma unroll
            for (int q = 0; q < 4; q++) {
                float cand = (q == 0) ? cnd0 : (q == 1) ? cnd1 : (q == 2) ? cnd2 : cnd3;
                int   col  = cb + j + 32 * q;
                unsigned mask = __ballot_sync(FULLMASK, cand > thr);
                if (mask) {   // warp-uniform; thr only changes when inserts happen
                    while (mask) {
                        int src = __ffs(mask) - 1; mask &= mask - 1;
                        float val = __shfl_sync(FULLMASK, cand, src);
                        int   ci  = __shfl_sync(FULLMASK, col,  src);
                        float pv  = __shfl_up_sync(FULLMASK, lv[r], 1);
                        int   pi  = __shfl_up_sync(FULLMASK, lidx[r], 1);
                        bool keep = (lv[r] >= val);
                        bool prevkeep = (j == 0) || (pv >= val);
                        if (!keep) {
                            lv[r]   = prevkeep ? val : pv;
                            lidx[r] = prevkeep ? ci  : pi;
                        }
                    }
                    thr = __shfl_sync(FULLMASK, lv[r], KNN - 1);
                }
            }
        }
    }

    // ---- fused epilogue: former k_stats (identical per-thread sum order) ----
    __syncthreads();                       // all warps done with GEMM phase
    int* sidx = (int*)rX4s;                // reuse dead smem (32*20 ints <= 8KB)
    #pragma unroll
    for (int r = 0; r < 4; r++)
        if (j < KNN) sidx[(rl0 + r) * KNN + j] = lidx[r];
    __syncthreads();

    {
        int tx = t & 63, ty = t >> 6;
        float* ssum = (float*)cP4;         // [4*64]
        float* sssq = ssum + 256;
        float sum = 0.f, ssq = 0.f;
        for (int ri = ty; ri < 32; ri += 4) {
            int row = rowbase + ri;
            float hcv = g_hc[(size_t)row * 64 + tx];
            float mx = NEG_INF, mn = -NEG_INF;
            #pragma unroll
            for (int k = 0; k < KNN; k++) {
                int jj = sidx[ri * KNN + k];
                float v = hcv + g_hn[(size_t)(b * NPTS + jj) * 64 + tx];
                sum += v; ssq = fmaf(v, v, ssq);
                mx = fmaxf(mx, v); mn = fminf(mn, v);
            }
            g_mmax[(size_t)row * 64 + tx] = mx;
            g_mmin[(size_t)row * 64 + tx] = mn;
        }
        ssum[ty * 64 + tx] = sum; sssq[ty * 64 + tx] = ssq;
        __syncthreads();
        if (ty == 0) {
            float s = ssum[tx] + ssum[64 + tx] + ssum[128 + tx] + ssum[192 + tx];
            float q = sssq[tx] + sssq[64 + tx] + sssq[128 + tx] + sssq[192 + tx];
            atomicAdd(&g_sum[tx],   (double)s);
            atomicAdd(&g_sumsq[tx], (double)q);
        }
    }
}

// ---------------- K5: finalize BN scale/shift ----------------
__global__ void k_final(const float* __restrict__ gamma, const float* __restrict__ beta) {
    int o = threadIdx.x;
    if (o < ODIM) {
        double cnt  = (double)ROWS_TOTAL * KNN;
        double mean = g_sum[o] / cnt;
        double var  = g_sumsq[o] / cnt - mean * mean;
        float sc = gamma[o] * rsqrtf((float)var + 1e-5f);
        g_scale[o] = sc;
        g_shift[o] = beta[o] - (float)mean * sc;
    }
}

// ---------------- K6: apply affine + LeakyReLU + transpose to [B,O,N] ----------------
__global__ void k_out(float* __restrict__ out) {
    __shared__ float smt[64][65];
    int tx = threadIdx.x, ty = threadIdx.y;   // block (64,4)
    int nb = blockIdx.x * 64;
    int b  = blockIdx.y;
    float sc = g_scale[tx], sh = g_shift[tx];
    #pragma unroll
    for (int i = 0; i < 16; i++) {
        int nl = ty + 4 * i;
        size_t rowoff = (size_t)(b * NPTS + nb + nl) * 64 + tx;
        float m = (sc >= 0.f) ? g_mmax[rowoff] : g_mmin[rowoff];
        float y = fmaf(m, sc, sh);
        y = (y >= 0.f) ? y : 0.2f * y;
        smt[nl][tx] = y;
    }
    __syncthreads();
    #pragma unroll
    for (int i = 0; i < 16; i++) {
        int o = ty + 4 * i;
        out[((size_t)(b * 64 + o)) * NPTS + nb + tx] = smt[tx][o];
    }
}

extern "C" void kernel_launch(void* const* d_in, const int* in_sizes, int n_in,
                              void* d_out, int out_size) {
    const float* x     = (const float*)d_in[0];
    const float* W     = (const float*)d_in[1];
    const float* bias  = (const float*)d_in[2];
    const float* gamma = (const float*)d_in[3];
    const float* beta  = (const float*)d_in[4];
    float* out = (float*)d_out;

    k_xx<<<ROWS_TOTAL / 4, 128>>>(x);
    k_pack<<<1024, 256>>>(x);
    k_hchn<<<ROWS_TOTAL / 32, 256, (128 * 17 + 32 * 16) * 16>>>(x, W, bias);
    k_topk<<<dim3(NPTS / 32, BATCH), 256>>>(x);
    k_final<<<1, 64>>>(gamma, beta);
    k_out<<<dim3(NPTS / 64, BATCH), dim3(64, 4)>>>(out);
}